// round 14
// baseline (speedup 1.0000x reference)
#include <cuda_runtime.h>
#include <math.h>

#define S_LEN 512
#define B_SZ  64
#define HID   512
#define G3    1536
#define EMB_D 256
#define M_ROWS (S_LEN * B_SZ)   // 32768

typedef unsigned long long ull;

// ---------------- packed f32x2 helpers --------------------------------------
__device__ __forceinline__ ull pk2(float lo, float hi) {
    ull r; asm("mov.b64 %0, {%1,%2};" : "=l"(r) : "f"(lo), "f"(hi)); return r;
}
__device__ __forceinline__ ull dup2(float v) { return pk2(v, v); }
__device__ __forceinline__ void ffma2(ull& d, ull a, ull b) {
    asm("fma.rn.f32x2 %0, %1, %2, %0;" : "+l"(d) : "l"(a), "l"(b));
}
__device__ __forceinline__ ull add2(ull a, ull b) {
    ull r; asm("add.rn.f32x2 %0, %1, %2;" : "=l"(r) : "l"(a), "l"(b)); return r;
}
__device__ __forceinline__ float2 unpk2(ull v) {
    float2 f; asm("mov.b64 {%0,%1}, %2;" : "=f"(f.x), "=f"(f.y) : "l"(v)); return f;
}

// ---------------- scratch (static device globals; no allocation) ------------
__device__ float g_xemb[(size_t)M_ROWS * EMB_D];   // 32 MB
__device__ float g_xg[(size_t)M_ROWS * G3];        // 192 MB
__device__ float g_ys[(size_t)M_ROWS * HID];       // 64 MB
__device__ unsigned int g_flags[4][64][32];         // one flag per 128B line

// ---------------- embedding gather ------------------------------------------
__global__ void embed_kernel(const int* __restrict__ x,
                             const float* __restrict__ emb,
                             float* __restrict__ out) {
    int w    = (blockIdx.x << 3) + (threadIdx.x >> 5);
    int lane = threadIdx.x & 31;
    int s = w >> 6, b = w & 63;
    int tok = x[b * S_LEN + s];
    float4* dst = (float4*)(out + (size_t)w * EMB_D);
    if (tok == 0) {
        float4 z = make_float4(0.f, 0.f, 0.f, 0.f);
        dst[lane] = z; dst[lane + 32] = z;
    } else {
        const float4* src = (const float4*)(emb + (size_t)tok * EMB_D);
        dst[lane] = src[lane]; dst[lane + 32] = src[lane + 32];
    }
}

// ---------------- C[M,N] = A[M,K] @ W[N,K]^T + bias[N] ----------------------
__global__ void __launch_bounds__(256, 2) gemm_bias_kernel(
    const float* __restrict__ A, const float* __restrict__ W,
    const float* __restrict__ bias, float* __restrict__ C,
    int M, int N, int K) {
    __shared__ float As[2][16][128];
    __shared__ float Bs[2][16][128];

    const int tid = threadIdx.x;
    const int n0 = blockIdx.x * 128;
    const int m0 = blockIdx.y * 128;
    const int tx = tid & 15, ty = tid >> 4;

    ull acc2[4][8];
#pragma unroll
    for (int p = 0; p < 4; p++)
#pragma unroll
        for (int j = 0; j < 8; j++) acc2[p][j] = 0ULL;

    const int KT = K >> 4;

#pragma unroll
    for (int i = 0; i < 2; i++) {
        int id = tid * 2 + i, row = id >> 2, kq = id & 3;
        float4 va = *(const float4*)(A + (size_t)(m0 + row) * K + kq * 4);
        float4 vb = *(const float4*)(W + (size_t)(n0 + row) * K + kq * 4);
        As[0][kq * 4 + 0][row] = va.x; As[0][kq * 4 + 1][row] = va.y;
        As[0][kq * 4 + 2][row] = va.z; As[0][kq * 4 + 3][row] = va.w;
        Bs[0][kq * 4 + 0][row] = vb.x; Bs[0][kq * 4 + 1][row] = vb.y;
        Bs[0][kq * 4 + 2][row] = vb.z; Bs[0][kq * 4 + 3][row] = vb.w;
    }
    __syncthreads();

    for (int kt = 0; kt < KT; ++kt) {
        const int cur = kt & 1;
        float4 pa[2], pb[2];
        const bool pf = (kt + 1) < KT;
        if (pf) {
#pragma unroll
            for (int i = 0; i < 2; i++) {
                int id = tid * 2 + i, row = id >> 2, kq = id & 3;
                pa[i] = *(const float4*)(A + (size_t)(m0 + row) * K + (kt + 1) * 16 + kq * 4);
                pb[i] = *(const float4*)(W + (size_t)(n0 + row) * K + (kt + 1) * 16 + kq * 4);
            }
        }
#pragma unroll
        for (int kk = 0; kk < 16; kk++) {
            ulonglong2 a01 = *(const ulonglong2*)&As[cur][kk][ty * 4];
            ulonglong2 a23 = *(const ulonglong2*)&As[cur][kk][64 + ty * 4];
            ull ap[4] = { a01.x, a01.y, a23.x, a23.y };
            float b[8];
            *(float4*)(b)     = *(const float4*)&Bs[cur][kk][tx * 4];
            *(float4*)(b + 4) = *(const float4*)&Bs[cur][kk][64 + tx * 4];
#pragma unroll
            for (int j = 0; j < 8; j++) {
                ull bd = dup2(b[j]);
#pragma unroll
                for (int p = 0; p < 4; p++) ffma2(acc2[p][j], ap[p], bd);
            }
        }
        if (pf) {
            const int nxt = cur ^ 1;
#pragma unroll
            for (int i = 0; i < 2; i++) {
                int id = tid * 2 + i, row = id >> 2, kq = id & 3;
                As[nxt][kq * 4 + 0][row] = pa[i].x; As[nxt][kq * 4 + 1][row] = pa[i].y;
                As[nxt][kq * 4 + 2][row] = pa[i].z; As[nxt][kq * 4 + 3][row] = pa[i].w;
                Bs[nxt][kq * 4 + 0][row] = pb[i].x; Bs[nxt][kq * 4 + 1][row] = pb[i].y;
                Bs[nxt][kq * 4 + 2][row] = pb[i].z; Bs[nxt][kq * 4 + 3][row] = pb[i].w;
            }
        }
        __syncthreads();
    }

    float4 bb0 = *(const float4*)&bias[n0 + tx * 4];
    float4 bb1 = *(const float4*)&bias[n0 + 64 + tx * 4];
#pragma unroll
    for (int p = 0; p < 4; p++) {
        float2 c[8];
#pragma unroll
        for (int j = 0; j < 8; j++) c[j] = unpk2(acc2[p][j]);
#pragma unroll
        for (int half = 0; half < 2; half++) {
            int i = 2 * p + half;
            int m = m0 + ((i < 4) ? (ty * 4 + i) : (64 + ty * 4 + i - 4));
            float e[8];
#pragma unroll
            for (int j = 0; j < 8; j++) e[j] = half ? c[j].y : c[j].x;
            float4 v0 = make_float4(e[0] + bb0.x, e[1] + bb0.y,
                                    e[2] + bb0.z, e[3] + bb0.w);
            float4 v1 = make_float4(e[4] + bb1.x, e[5] + bb1.y,
                                    e[6] + bb1.z, e[7] + bb1.w);
            *(float4*)(C + (size_t)m * N + n0 + tx * 4)      = v0;
            *(float4*)(C + (size_t)m * N + n0 + 64 + tx * 4) = v1;
        }
    }
}

// ---------------- GRU recurrence ---------------------------------------------
// 256 blocks = 4 batch groups (16 rows) x 64 dim groups (8 dims), 256 threads,
// OCCUPANCY 2: co-resident blocks (bid, bid+148) are in different batch groups
// (bg = bid>>6), so one chain's poll/LDG/barrier latency overlaps the other's
// FFMA2 issue on the same SMSPs.
// Warp w (0..7) owns k in [64w, 64w+64); lanes 0-15 even k, 16-31 odd k.
// Lane: d = lane&7 (owned dim), rh = (lane>>3)&1 (row half: rows rh*8..rh*8+7).
// Wsh [512][24] gate-major (col = g*8+d): even/odd halves on disjoint banks.
// hsh [512][20]: broadcast LDS.128 h loads, conflict-free staging.
#define WSTR 24
#define HS 20
#define PSTR 9     // float4 stride per (warp,row)
#define GRU_SMEM_FLOATS (512 * WSTR + 512 * HS + 8 * 16 * PSTR * 4)
#define GRU_SMEM_BYTES  (GRU_SMEM_FLOATS * 4)

__device__ __forceinline__ unsigned ld_acq(const unsigned* p) {
    unsigned v;
    asm volatile("ld.global.acquire.gpu.u32 %0, [%1];" : "=r"(v) : "l"(p) : "memory");
    return v;
}
__device__ __forceinline__ void st_rel(unsigned* p, unsigned v) {
    asm volatile("st.global.release.gpu.u32 [%0], %1;" :: "l"(p), "r"(v) : "memory");
}

__global__ void __launch_bounds__(256, 2) gru_kernel(
    const float* __restrict__ xg,    // [S][64][1536]
    const float* __restrict__ Whh,   // [1536][512]
    const float* __restrict__ bhh,   // [1536]
    float* __restrict__ ys)          // [S][64][512]
{
    extern __shared__ float sm[];
    float* Wsh  = sm;                          // 512*24
    float* hsh  = Wsh + 512 * WSTR;            // 512*20
    float* part = hsh + 512 * HS;              // 8*16*9 float4
    __shared__ unsigned sh_base;

    const int tid = threadIdx.x;
    const int dg  = blockIdx.x & 63;           // 64 dim groups (8 dims)
    const int bg  = blockIdx.x >> 6;           // 4 batch groups (16 rows)
    const int rowBase = bg * 16;
    const int dimBase = dg * 8;

    if (tid == 0) sh_base = *(volatile unsigned*)&g_flags[bg][dg][0];

    // load W_hh slice: 24 gate cols (col = g*8 + d), k-major, stride 24
    for (int idx = tid; idx < 24 * 512; idx += 256) {
        int col = idx >> 9;       // 0..23
        int k   = idx & 511;
        int g = col >> 3, d = col & 7;
        int grow = g * 512 + dimBase + d;
        Wsh[k * WSTR + col] = Whh[(size_t)grow * 512 + k];
    }

    // gating role (tid < 128): one thread per (row, dim); h_old in a register
    const int myrow = (tid >> 3) & 15;
    const int mydl  = tid & 7;
    const int mydim = dimBase + mydl;
    float b_r = 0.f, b_z = 0.f, b_n = 0.f;
    float h_old = 0.f;
    if (tid < 128) {
        b_r = bhh[mydim]; b_z = bhh[512 + mydim]; b_n = bhh[1024 + mydim];
    }

    // compute role
    const int w    = tid >> 5;            // warp 0..7, k chunk [64w, 64w+64)
    const int lane = tid & 31;
    const int half = lane >> 4;           // 0: even k, 1: odd k
    const int l    = lane & 15;
    const int d    = l & 7;               // owned dim (local)
    const int rh   = l >> 3;              // row half (rows rh*8 .. rh*8+7)
    const int k0   = w * 64;

    __syncthreads();
    const unsigned base = sh_base;

    for (int t = 0; t < S_LEN; ++t) {
        // xg prefetch for gating
        float xr = 0.f, xz = 0.f, xn = 0.f;
        if (tid < 128) {
            size_t xbase = ((size_t)t * 64 + rowBase + myrow) * G3 + mydim;
            xr = xg[xbase]; xz = xg[xbase + 512]; xn = xg[xbase + 1024];
        }

        // ---- warp-private h staging: poll 8 producer flags in parallel ----
        if (t == 0) {
            for (int idx = lane; idx < 64 * HS; idx += 32)
                hsh[k0 * HS + idx] = 0.f;
            __syncwarp();
        } else {
            const unsigned target = base + (unsigned)t;
            if (lane < 8) {
                const unsigned* fp = &g_flags[bg][8 * w + lane][0];
                while ((int)(ld_acq(fp) - target) < 0) { }
            }
            __syncwarp();
            const float4* hsrc4 = (const float4*)(ys + ((size_t)(t - 1) * 64 + rowBase) * HID);
            float4 v[8];
#pragma unroll
            for (int i = 0; i < 8; i++) {
                int idx = i * 32 + lane;
                int r = idx & 15, fq = idx >> 4;
                v[i] = __ldcg(hsrc4 + (size_t)r * 128 + w * 16 + fq);
            }
#pragma unroll
            for (int i = 0; i < 8; i++) {
                int idx = i * 32 + lane;
                int r = idx & 15, fq = idx >> 4;
                int kb = k0 + fq * 4;
                hsh[(kb + 0) * HS + r] = v[i].x;
                hsh[(kb + 1) * HS + r] = v[i].y;
                hsh[(kb + 2) * HS + r] = v[i].z;
                hsh[(kb + 3) * HS + r] = v[i].w;
            }
            __syncwarp();
        }

        // ---- GEMM: lane owns dim d, rows rh*8..+8 (4 pairs), 3 gates ----
        ull acc[12];   // [rowpair j][gate g] = acc[j*3+g]
#pragma unroll
        for (int i = 0; i < 12; i++) acc[i] = 0ULL;
#pragma unroll 4
        for (int it = 0; it < 32; ++it) {
            const int k = k0 + 2 * it + half;
            const float* wk = Wsh + k * WSTR + d;
            ull wr2 = dup2(wk[0]);
            ull wz2 = dup2(wk[8]);
            ull wn2 = dup2(wk[16]);
            const float* hk = hsh + k * HS + rh * 8;
            ulonglong2 hq0 = *(const ulonglong2*)(hk);
            ulonglong2 hq1 = *(const ulonglong2*)(hk + 4);
            ull hp[4] = { hq0.x, hq0.y, hq1.x, hq1.y };
#pragma unroll
            for (int j = 0; j < 4; j++) {
                ffma2(acc[j * 3 + 0], hp[j], wr2);
                ffma2(acc[j * 3 + 1], hp[j], wz2);
                ffma2(acc[j * 3 + 2], hp[j], wn2);
            }
        }

        // ---- merge halves (even k + odd k) ----
#pragma unroll
        for (int i = 0; i < 12; i++) {
            ull o = __shfl_down_sync(0xffffffffu, acc[i], 16);
            acc[i] = add2(acc[i], o);   // lanes<16 hold full 64-k sums
        }

        // ---- write partials (lanes < 16): float4 (r,z,n,0) per row ----
        if (half == 0) {
#pragma unroll
            for (int j = 0; j < 4; j++) {
                float2 r2 = unpk2(acc[j * 3 + 0]);
                float2 z2 = unpk2(acc[j * 3 + 1]);
                float2 n2 = unpk2(acc[j * 3 + 2]);
                int row0 = rh * 8 + 2 * j;
                float* pp0 = part + (((w * 16 + row0) * PSTR + d) << 2);
                float* pp1 = part + (((w * 16 + row0 + 1) * PSTR + d) << 2);
                *(float4*)pp0 = make_float4(r2.x, z2.x, n2.x, 0.f);
                *(float4*)pp1 = make_float4(r2.y, z2.y, n2.y, 0.f);
            }
        }
        __syncthreads();

        // ---- reduce 8 k-groups + gate, one thread per (row, dim) ----
        if (tid < 128) {
            float hr = b_r, hz = b_z, hn = b_n;
#pragma unroll
            for (int kk = 0; kk < 8; kk++) {
                float4 p = *(const float4*)(part +
                    (((kk * 16 + myrow) * PSTR + mydl) << 2));
                hr += p.x; hz += p.y; hn += p.z;
            }
            float er = __expf(-(xr + hr));
            float rr = __fdividef(1.f, 1.f + er);
            float ez = __expf(-(xz + hz));
            float zz = __fdividef(1.f, 1.f + ez);
            float an = xn + rr * hn;
            float e2 = __expf(2.f * an);
            float nn = 1.f - __fdividef(2.f, e2 + 1.f);   // tanh(an)
            float hnew = (1.f - zz) * nn + zz * h_old;
            h_old = hnew;
            ys[((size_t)t * 64 + rowBase + myrow) * HID + mydim] = hnew;
        }

        __syncthreads();
        if (tid == 0) st_rel(&g_flags[bg][dg][0], base + (unsigned)t + 1u);
    }
}

// ---------------- final FC + sigmoid ----------------------------------------
__global__ void fc_kernel(const float* __restrict__ ys,
                          const float* __restrict__ Wfc,
                          const float* __restrict__ bfc,
                          float* __restrict__ out) {
    int b = blockIdx.x, tid = threadIdx.x;
    const float* h = ys + ((size_t)(S_LEN - 1) * 64 + b) * HID;
    float s = 0.f;
    for (int i = tid; i < HID; i += 128) s += h[i] * Wfc[i];
#pragma unroll
    for (int o = 16; o; o >>= 1) s += __shfl_down_sync(0xffffffffu, s, o);
    __shared__ float ps[4];
    if ((tid & 31) == 0) ps[tid >> 5] = s;
    __syncthreads();
    if (tid == 0) {
        float v = ps[0] + ps[1] + ps[2] + ps[3] + bfc[0];
        out[b] = 1.f / (1.f + expf(-v));
    }
}

// ---------------- launch ----------------------------------------------------
extern "C" void kernel_launch(void* const* d_in, const int* in_sizes, int n_in,
                              void* d_out, int out_size) {
    (void)in_sizes; (void)n_in; (void)out_size;
    const int*   x    = (const int*)  d_in[0];
    const float* emb  = (const float*)d_in[1];
    const float* Wih0 = (const float*)d_in[2];
    const float* Whh0 = (const float*)d_in[3];
    const float* bih0 = (const float*)d_in[4];
    const float* bhh0 = (const float*)d_in[5];
    const float* Wih1 = (const float*)d_in[6];
    const float* Whh1 = (const float*)d_in[7];
    const float* bih1 = (const float*)d_in[8];
    const float* bhh1 = (const float*)d_in[9];
    const float* Wfc  = (const float*)d_in[10];
    const float* bfc  = (const float*)d_in[11];
    float* out = (float*)d_out;

    float *xemb, *xgbuf, *ysbuf;
    cudaGetSymbolAddress((void**)&xemb,  g_xemb);
    cudaGetSymbolAddress((void**)&xgbuf, g_xg);
    cudaGetSymbolAddress((void**)&ysbuf, g_ys);

    cudaFuncSetAttribute(gru_kernel, cudaFuncAttributeMaxDynamicSharedMemorySize,
                         GRU_SMEM_BYTES);

    embed_kernel<<<4096, 256>>>(x, emb, xemb);
    gemm_bias_kernel<<<dim3(G3 / 128, M_ROWS / 128), 256>>>(
        xemb, Wih0, bih0, xgbuf, M_ROWS, G3, EMB_D);
    gru_kernel<<<256, 256, GRU_SMEM_BYTES>>>(xgbuf, Whh0, bhh0, ysbuf);
    gemm_bias_kernel<<<dim3(G3 / 128, M_ROWS / 128), 256>>>(
        ysbuf, Wih1, bih1, xgbuf, M_ROWS, G3, HID);
    gru_kernel<<<256, 256, GRU_SMEM_BYTES>>>(xgbuf, Whh1, bhh1, ysbuf);
    fc_kernel<<<64, 128>>>(ysbuf, Wfc, bfc, out);
}

// round 15
// speedup vs baseline: 1.7078x; 1.7078x over previous
#include <cuda_runtime.h>
#include <math.h>

#define S_LEN 512
#define B_SZ  64
#define HID   512
#define G3    1536
#define EMB_D 256
#define M_ROWS (S_LEN * B_SZ)   // 32768

typedef unsigned long long ull;

// ---------------- packed f32x2 helpers --------------------------------------
__device__ __forceinline__ ull pk2(float lo, float hi) {
    ull r; asm("mov.b64 %0, {%1,%2};" : "=l"(r) : "f"(lo), "f"(hi)); return r;
}
__device__ __forceinline__ ull dup2(float v) { return pk2(v, v); }
__device__ __forceinline__ void ffma2(ull& d, ull a, ull b) {
    asm("fma.rn.f32x2 %0, %1, %2, %0;" : "+l"(d) : "l"(a), "l"(b));
}
__device__ __forceinline__ ull add2(ull a, ull b) {
    ull r; asm("add.rn.f32x2 %0, %1, %2;" : "=l"(r) : "l"(a), "l"(b)); return r;
}
__device__ __forceinline__ float2 unpk2(ull v) {
    float2 f; asm("mov.b64 {%0,%1}, %2;" : "=f"(f.x), "=f"(f.y) : "l"(v)); return f;
}

// ---------------- scratch (static device globals; no allocation) ------------
__device__ float g_xemb[(size_t)M_ROWS * EMB_D];   // 32 MB
__device__ float g_xg[(size_t)M_ROWS * G3];        // 192 MB
__device__ float g_ys[(size_t)M_ROWS * HID];       // 64 MB
__device__ unsigned int g_flags[4][32][32];         // one flag per 128B line

// ---------------- embedding gather ------------------------------------------
__global__ void embed_kernel(const int* __restrict__ x,
                             const float* __restrict__ emb,
                             float* __restrict__ out) {
    int w    = (blockIdx.x << 3) + (threadIdx.x >> 5);
    int lane = threadIdx.x & 31;
    int s = w >> 6, b = w & 63;
    int tok = x[b * S_LEN + s];
    float4* dst = (float4*)(out + (size_t)w * EMB_D);
    if (tok == 0) {
        float4 z = make_float4(0.f, 0.f, 0.f, 0.f);
        dst[lane] = z; dst[lane + 32] = z;
    } else {
        const float4* src = (const float4*)(emb + (size_t)tok * EMB_D);
        dst[lane] = src[lane]; dst[lane + 32] = src[lane + 32];
    }
}

// ---------------- C[M,N] = A[M,K] @ W[N,K]^T + bias[N] ----------------------
__global__ void __launch_bounds__(256, 2) gemm_bias_kernel(
    const float* __restrict__ A, const float* __restrict__ W,
    const float* __restrict__ bias, float* __restrict__ C,
    int M, int N, int K) {
    __shared__ float As[2][16][128];
    __shared__ float Bs[2][16][128];

    const int tid = threadIdx.x;
    const int n0 = blockIdx.x * 128;
    const int m0 = blockIdx.y * 128;
    const int tx = tid & 15, ty = tid >> 4;

    ull acc2[4][8];
#pragma unroll
    for (int p = 0; p < 4; p++)
#pragma unroll
        for (int j = 0; j < 8; j++) acc2[p][j] = 0ULL;

    const int KT = K >> 4;

#pragma unroll
    for (int i = 0; i < 2; i++) {
        int id = tid * 2 + i, row = id >> 2, kq = id & 3;
        float4 va = *(const float4*)(A + (size_t)(m0 + row) * K + kq * 4);
        float4 vb = *(const float4*)(W + (size_t)(n0 + row) * K + kq * 4);
        As[0][kq * 4 + 0][row] = va.x; As[0][kq * 4 + 1][row] = va.y;
        As[0][kq * 4 + 2][row] = va.z; As[0][kq * 4 + 3][row] = va.w;
        Bs[0][kq * 4 + 0][row] = vb.x; Bs[0][kq * 4 + 1][row] = vb.y;
        Bs[0][kq * 4 + 2][row] = vb.z; Bs[0][kq * 4 + 3][row] = vb.w;
    }
    __syncthreads();

    for (int kt = 0; kt < KT; ++kt) {
        const int cur = kt & 1;
        float4 pa[2], pb[2];
        const bool pf = (kt + 1) < KT;
        if (pf) {
#pragma unroll
            for (int i = 0; i < 2; i++) {
                int id = tid * 2 + i, row = id >> 2, kq = id & 3;
                pa[i] = *(const float4*)(A + (size_t)(m0 + row) * K + (kt + 1) * 16 + kq * 4);
                pb[i] = *(const float4*)(W + (size_t)(n0 + row) * K + (kt + 1) * 16 + kq * 4);
            }
        }
#pragma unroll
        for (int kk = 0; kk < 16; kk++) {
            ulonglong2 a01 = *(const ulonglong2*)&As[cur][kk][ty * 4];
            ulonglong2 a23 = *(const ulonglong2*)&As[cur][kk][64 + ty * 4];
            ull ap[4] = { a01.x, a01.y, a23.x, a23.y };
            float b[8];
            *(float4*)(b)     = *(const float4*)&Bs[cur][kk][tx * 4];
            *(float4*)(b + 4) = *(const float4*)&Bs[cur][kk][64 + tx * 4];
#pragma unroll
            for (int j = 0; j < 8; j++) {
                ull bd = dup2(b[j]);
#pragma unroll
                for (int p = 0; p < 4; p++) ffma2(acc2[p][j], ap[p], bd);
            }
        }
        if (pf) {
            const int nxt = cur ^ 1;
#pragma unroll
            for (int i = 0; i < 2; i++) {
                int id = tid * 2 + i, row = id >> 2, kq = id & 3;
                As[nxt][kq * 4 + 0][row] = pa[i].x; As[nxt][kq * 4 + 1][row] = pa[i].y;
                As[nxt][kq * 4 + 2][row] = pa[i].z; As[nxt][kq * 4 + 3][row] = pa[i].w;
                Bs[nxt][kq * 4 + 0][row] = pb[i].x; Bs[nxt][kq * 4 + 1][row] = pb[i].y;
                Bs[nxt][kq * 4 + 2][row] = pb[i].z; Bs[nxt][kq * 4 + 3][row] = pb[i].w;
            }
        }
        __syncthreads();
    }

    float4 bb0 = *(const float4*)&bias[n0 + tx * 4];
    float4 bb1 = *(const float4*)&bias[n0 + 64 + tx * 4];
#pragma unroll
    for (int p = 0; p < 4; p++) {
        float2 c[8];
#pragma unroll
        for (int j = 0; j < 8; j++) c[j] = unpk2(acc2[p][j]);
#pragma unroll
        for (int half = 0; half < 2; half++) {
            int i = 2 * p + half;
            int m = m0 + ((i < 4) ? (ty * 4 + i) : (64 + ty * 4 + i - 4));
            float e[8];
#pragma unroll
            for (int j = 0; j < 8; j++) e[j] = half ? c[j].y : c[j].x;
            float4 v0 = make_float4(e[0] + bb0.x, e[1] + bb0.y,
                                    e[2] + bb0.z, e[3] + bb0.w);
            float4 v1 = make_float4(e[4] + bb1.x, e[5] + bb1.y,
                                    e[6] + bb1.z, e[7] + bb1.w);
            *(float4*)(C + (size_t)m * N + n0 + tx * 4)      = v0;
            *(float4*)(C + (size_t)m * N + n0 + 64 + tx * 4) = v1;
        }
    }
}

// ---------------- GRU recurrence ---------------------------------------------
// R13 skeleton (128 blocks = 4 bg x 32 dg, 512 thr, W in regs) with:
//  * part DOUBLE-BUFFERED by t parity -> the post-gate __syncthreads removed
//  * flag released per-gating-warp via red.release.add (8 arrivals/step);
//    consumers poll flag - base >= 8*t. Early warps publish early.
#define HS 20
#define P4STRIDE 17
#define PBUF_FLOATS (16 * 16 * P4STRIDE * 4)
#define GRU_SMEM_FLOATS (512 * HS + 2 * PBUF_FLOATS)
#define GRU_SMEM_BYTES  (GRU_SMEM_FLOATS * 4)

__device__ __forceinline__ unsigned ld_acq(const unsigned* p) {
    unsigned v;
    asm volatile("ld.global.acquire.gpu.u32 %0, [%1];" : "=r"(v) : "l"(p) : "memory");
    return v;
}
__device__ __forceinline__ void red_rel_add(unsigned* p, unsigned v) {
    asm volatile("red.release.gpu.global.add.u32 [%0], %1;" :: "l"(p), "r"(v) : "memory");
}

__global__ void __launch_bounds__(512, 1) gru_kernel(
    const float* __restrict__ xg,    // [S][64][1536]
    const float* __restrict__ Whh,   // [1536][512]
    const float* __restrict__ bhh,   // [1536]
    float* __restrict__ ys)          // [S][64][512]
{
    extern __shared__ float sm[];
    float* hsh   = sm;                          // 512*20
    float* part0 = hsh + 512 * HS;              // buffer 0
    float* part1 = part0 + PBUF_FLOATS;         // buffer 1
    __shared__ unsigned sh_base;

    const int tid = threadIdx.x;
    const int bg  = blockIdx.x & 3;
    const int dg  = blockIdx.x >> 2;
    const int rowBase = bg * 16;
    const int dimBase = dg * 16;

    if (tid == 0) sh_base = *(volatile unsigned*)&g_flags[bg][dg][0];

    // gating role (tid < 256): one thread per (row, dim); h_old in a register
    const int myrow = (tid >> 4) & 15;
    const int mydl  = tid & 15;
    const int mydim = dimBase + mydl;
    float b_r = 0.f, b_z = 0.f, b_n = 0.f;
    float h_old = 0.f;
    if (tid < 256) {
        b_r = bhh[mydim]; b_z = bhh[512 + mydim]; b_n = bhh[1024 + mydim];
    }

    // compute role
    const int w    = tid >> 5;            // warp 0..15, k chunk [32w, 32w+32)
    const int lane = tid & 31;
    const int half = lane >> 4;           // 0: even k, 1: odd k
    const int l    = lane & 15;           // owned dim (local)
    const int k0   = w * 32;

    // W_hh slice -> registers: wreg[it*3+g] = Whh[g*512+dimBase+l][k0+2*it+half]
    float wreg[48];
#pragma unroll
    for (int it = 0; it < 16; ++it) {
        const int k = k0 + 2 * it + half;
#pragma unroll
        for (int g = 0; g < 3; g++)
            wreg[it * 3 + g] = Whh[(size_t)(g * 512 + dimBase + l) * 512 + k];
    }

    __syncthreads();
    const unsigned base = sh_base;

    for (int t = 0; t < S_LEN; ++t) {
        float* part = (t & 1) ? part1 : part0;

        // xg prefetch for gating
        float xr = 0.f, xz = 0.f, xn = 0.f;
        if (tid < 256) {
            size_t xbase = ((size_t)t * 64 + rowBase + myrow) * G3 + mydim;
            xr = xg[xbase]; xz = xg[xbase + 512]; xn = xg[xbase + 1024];
        }

        // ---- warp-private h staging (h stored [k][row], stride 20) ----
        if (t == 0) {
            for (int idx = lane; idx < 32 * HS; idx += 32)
                hsh[k0 * HS + idx] = 0.f;
            __syncwarp();
        } else {
            const unsigned target = base + 8u * (unsigned)t;
            const float4* hsrc4 = (const float4*)(ys + ((size_t)(t - 1) * 64 + rowBase) * HID);
            float4 v[2][2];
#pragma unroll
            for (int j = 0; j < 2; j++) {
                const int c = 2 * w + j;   // producer chunk (16 dims = 16 k)
                const unsigned* fp = &g_flags[bg][c][0];
                while ((int)(ld_acq(fp) - target) < 0) { }
#pragma unroll
                for (int i = 0; i < 2; i++) {
                    int idx = i * 32 + lane;
                    int r = idx & 15, fq = idx >> 4;
                    v[j][i] = __ldcg(hsrc4 + (size_t)r * 128 + c * 4 + fq);
                }
            }
#pragma unroll
            for (int j = 0; j < 2; j++) {
                const int c = 2 * w + j;
#pragma unroll
                for (int i = 0; i < 2; i++) {
                    int idx = i * 32 + lane;
                    int r = idx & 15, fq = idx >> 4;
                    int kb = c * 16 + fq * 4;
                    hsh[(kb + 0) * HS + r] = v[j][i].x;
                    hsh[(kb + 1) * HS + r] = v[j][i].y;
                    hsh[(kb + 2) * HS + r] = v[j][i].z;
                    hsh[(kb + 3) * HS + r] = v[j][i].w;
                }
            }
            __syncwarp();
        }

        // ---- GEMM: lane owns dim l, 16 rows (8 row-pairs), 3 gates ----
        ull acc[24];   // [rowpair j][gate g] = acc[j*3+g]
#pragma unroll
        for (int i = 0; i < 24; i++) acc[i] = 0ULL;
#pragma unroll 4
        for (int it = 0; it < 16; ++it) {
            const int k = k0 + 2 * it + half;
            ull wr2 = dup2(wreg[it * 3 + 0]);
            ull wz2 = dup2(wreg[it * 3 + 1]);
            ull wn2 = dup2(wreg[it * 3 + 2]);
            const float* hk = hsh + k * HS;
            ulonglong2 hq[4];
#pragma unroll
            for (int q = 0; q < 4; q++) hq[q] = *(const ulonglong2*)(hk + 4 * q);
            ull hp[8] = { hq[0].x, hq[0].y, hq[1].x, hq[1].y,
                          hq[2].x, hq[2].y, hq[3].x, hq[3].y };
#pragma unroll
            for (int j = 0; j < 8; j++) {
                ffma2(acc[j * 3 + 0], hp[j], wr2);
                ffma2(acc[j * 3 + 1], hp[j], wz2);
                ffma2(acc[j * 3 + 2], hp[j], wn2);
            }
        }

        // ---- merge halves (even k + odd k) ----
#pragma unroll
        for (int i = 0; i < 24; i++) {
            ull o = __shfl_down_sync(0xffffffffu, acc[i], 16);
            acc[i] = add2(acc[i], o);   // lanes<16 hold full 32-k sums
        }

        // ---- write partials (lanes < 16): float4 (r,z,n,0) per row ----
        if (half == 0) {
#pragma unroll
            for (int j = 0; j < 8; j++) {
                float2 r2 = unpk2(acc[j * 3 + 0]);
                float2 z2 = unpk2(acc[j * 3 + 1]);
                float2 n2 = unpk2(acc[j * 3 + 2]);
                float* pp0 = part + (((w * 16 + 2 * j) * P4STRIDE + l) << 2);
                float* pp1 = part + (((w * 16 + 2 * j + 1) * P4STRIDE + l) << 2);
                *(float4*)pp0 = make_float4(r2.x, z2.x, n2.x, 0.f);
                *(float4*)pp1 = make_float4(r2.y, z2.y, n2.y, 0.f);
            }
        }
        __syncthreads();   // the ONLY block barrier per step

        // ---- reduce 16 k-groups + gate, one thread per (row, dim) ----
        if (tid < 256) {
            float hr = b_r, hz = b_z, hn = b_n;
#pragma unroll
            for (int kk = 0; kk < 16; kk++) {
                float4 p = *(const float4*)(part +
                    (((kk * 16 + myrow) * P4STRIDE + mydl) << 2));
                hr += p.x; hz += p.y; hn += p.z;
            }
            float er = __expf(-(xr + hr));
            float rr = __fdividef(1.f, 1.f + er);
            float ez = __expf(-(xz + hz));
            float zz = __fdividef(1.f, 1.f + ez);
            float an = xn + rr * hn;
            float e2 = __expf(2.f * an);
            float nn = 1.f - __fdividef(2.f, e2 + 1.f);   // tanh(an)
            float hnew = (1.f - zz) * nn + zz * h_old;
            h_old = hnew;
            ys[((size_t)t * 64 + rowBase + myrow) * HID + mydim] = hnew;
            // publish: each gating warp (2 rows x 16 dims) adds 1 (8/step total)
            __syncwarp();
            if (lane == 0) red_rel_add(&g_flags[bg][dg][0], 1u);
        }
    }
}

// ---------------- final FC + sigmoid ----------------------------------------
__global__ void fc_kernel(const float* __restrict__ ys,
                          const float* __restrict__ Wfc,
                          const float* __restrict__ bfc,
                          float* __restrict__ out) {
    int b = blockIdx.x, tid = threadIdx.x;
    const float* h = ys + ((size_t)(S_LEN - 1) * 64 + b) * HID;
    float s = 0.f;
    for (int i = tid; i < HID; i += 128) s += h[i] * Wfc[i];
#pragma unroll
    for (int o = 16; o; o >>= 1) s += __shfl_down_sync(0xffffffffu, s, o);
    __shared__ float ps[4];
    if ((tid & 31) == 0) ps[tid >> 5] = s;
    __syncthreads();
    if (tid == 0) {
        float v = ps[0] + ps[1] + ps[2] + ps[3] + bfc[0];
        out[b] = 1.f / (1.f + expf(-v));
    }
}

// ---------------- launch ----------------------------------------------------
extern "C" void kernel_launch(void* const* d_in, const int* in_sizes, int n_in,
                              void* d_out, int out_size) {
    (void)in_sizes; (void)n_in; (void)out_size;
    const int*   x    = (const int*)  d_in[0];
    const float* emb  = (const float*)d_in[1];
    const float* Wih0 = (const float*)d_in[2];
    const float* Whh0 = (const float*)d_in[3];
    const float* bih0 = (const float*)d_in[4];
    const float* bhh0 = (const float*)d_in[5];
    const float* Wih1 = (const float*)d_in[6];
    const float* Whh1 = (const float*)d_in[7];
    const float* bih1 = (const float*)d_in[8];
    const float* bhh1 = (const float*)d_in[9];
    const float* Wfc  = (const float*)d_in[10];
    const float* bfc  = (const float*)d_in[11];
    float* out = (float*)d_out;

    float *xemb, *xgbuf, *ysbuf;
    cudaGetSymbolAddress((void**)&xemb,  g_xemb);
    cudaGetSymbolAddress((void**)&xgbuf, g_xg);
    cudaGetSymbolAddress((void**)&ysbuf, g_ys);

    cudaFuncSetAttribute(gru_kernel, cudaFuncAttributeMaxDynamicSharedMemorySize,
                         GRU_SMEM_BYTES);

    embed_kernel<<<4096, 256>>>(x, emb, xemb);
    gemm_bias_kernel<<<dim3(G3 / 128, M_ROWS / 128), 256>>>(
        xemb, Wih0, bih0, xgbuf, M_ROWS, G3, EMB_D);
    gru_kernel<<<128, 512, GRU_SMEM_BYTES>>>(xgbuf, Whh0, bhh0, ysbuf);
    gemm_bias_kernel<<<dim3(G3 / 128, M_ROWS / 128), 256>>>(
        ysbuf, Wih1, bih1, xgbuf, M_ROWS, G3, HID);
    gru_kernel<<<128, 512, GRU_SMEM_BYTES>>>(xgbuf, Whh1, bhh1, ysbuf);
    fc_kernel<<<64, 128>>>(ysbuf, Wfc, bfc, out);
}

// round 16
// speedup vs baseline: 1.7991x; 1.0534x over previous
#include <cuda_runtime.h>
#include <math.h>

#define S_LEN 512
#define B_SZ  64
#define HID   512
#define G3    1536
#define EMB_D 256
#define M_ROWS (S_LEN * B_SZ)   // 32768

typedef unsigned long long ull;
typedef unsigned int uint32;

// ---------------- packed f32x2 helpers (GRU) ---------------------------------
__device__ __forceinline__ ull pk2(float lo, float hi) {
    ull r; asm("mov.b64 %0, {%1,%2};" : "=l"(r) : "f"(lo), "f"(hi)); return r;
}
__device__ __forceinline__ ull dup2(float v) { return pk2(v, v); }
__device__ __forceinline__ void ffma2(ull& d, ull a, ull b) {
    asm("fma.rn.f32x2 %0, %1, %2, %0;" : "+l"(d) : "l"(a), "l"(b));
}
__device__ __forceinline__ ull add2(ull a, ull b) {
    ull r; asm("add.rn.f32x2 %0, %1, %2;" : "=l"(r) : "l"(a), "l"(b)); return r;
}
__device__ __forceinline__ float2 unpk2(ull v) {
    float2 f; asm("mov.b64 {%0,%1}, %2;" : "=f"(f.x), "=f"(f.y) : "l"(v)); return f;
}

// ---------------- tf32 helpers ------------------------------------------------
__device__ __forceinline__ float tf32_rna(float x) {
    uint32 u; asm("cvt.rna.tf32.f32 %0, %1;" : "=r"(u) : "f"(x));
    return __uint_as_float(u);
}
__device__ __forceinline__ void mma_tf32(float* c, const uint32* a,
                                         uint32 b0, uint32 b1) {
    asm volatile(
        "mma.sync.aligned.m16n8k8.row.col.f32.tf32.tf32.f32 "
        "{%0,%1,%2,%3}, {%4,%5,%6,%7}, {%8,%9}, {%0,%1,%2,%3};"
        : "+f"(c[0]), "+f"(c[1]), "+f"(c[2]), "+f"(c[3])
        : "r"(a[0]), "r"(a[1]), "r"(a[2]), "r"(a[3]), "r"(b0), "r"(b1));
}

// ---------------- scratch (static device globals; no allocation) ------------
__device__ float g_ahi[(size_t)M_ROWS * 512];      // 64 MB (A hi, K<=512)
__device__ float g_alo[(size_t)M_ROWS * 512];      // 64 MB (A lo)
__device__ float g_w0hi[G3 * EMB_D], g_w0lo[G3 * EMB_D];
__device__ float g_w1hi[G3 * HID],  g_w1lo[G3 * HID];
__device__ float g_xg[(size_t)M_ROWS * G3];        // 192 MB
__device__ float g_ys[(size_t)M_ROWS * HID];       // 64 MB
__device__ unsigned int g_flags[4][32][32];         // one flag per 128B line

// ---------------- tf32 split (elementwise, float4) ---------------------------
__global__ void split_kernel(const float* __restrict__ src,
                             float* __restrict__ hi, float* __restrict__ lo,
                             int n4) {
    int i = blockIdx.x * blockDim.x + threadIdx.x;
    if (i >= n4) return;
    float4 v = ((const float4*)src)[i];
    float4 h, l;
    h.x = tf32_rna(v.x); l.x = tf32_rna(v.x - h.x);
    h.y = tf32_rna(v.y); l.y = tf32_rna(v.y - h.y);
    h.z = tf32_rna(v.z); l.z = tf32_rna(v.z - h.z);
    h.w = tf32_rna(v.w); l.w = tf32_rna(v.w - h.w);
    ((float4*)hi)[i] = h;
    ((float4*)lo)[i] = l;
}

// ---------------- embedding gather + tf32 split -------------------------------
__global__ void embed_split_kernel(const int* __restrict__ x,
                                   const float* __restrict__ emb,
                                   float* __restrict__ ahi,
                                   float* __restrict__ alo) {
    int w    = (blockIdx.x << 3) + (threadIdx.x >> 5);  // row m = s*64+b
    int lane = threadIdx.x & 31;
    int s = w >> 6, b = w & 63;
    int tok = x[b * S_LEN + s];
    float4* dh = (float4*)(ahi + (size_t)w * EMB_D);
    float4* dl = (float4*)(alo + (size_t)w * EMB_D);
    if (tok == 0) {
        float4 z = make_float4(0.f, 0.f, 0.f, 0.f);
        dh[lane] = z; dh[lane + 32] = z;
        dl[lane] = z; dl[lane + 32] = z;
    } else {
        const float4* src = (const float4*)(emb + (size_t)tok * EMB_D);
#pragma unroll
        for (int i = 0; i < 2; i++) {
            float4 v = src[lane + 32 * i];
            float4 h, l;
            h.x = tf32_rna(v.x); l.x = tf32_rna(v.x - h.x);
            h.y = tf32_rna(v.y); l.y = tf32_rna(v.y - h.y);
            h.z = tf32_rna(v.z); l.z = tf32_rna(v.z - h.z);
            h.w = tf32_rna(v.w); l.w = tf32_rna(v.w - h.w);
            dh[lane + 32 * i] = h;
            dl[lane + 32 * i] = l;
        }
    }
}

// ---------------- tensor-core GEMM: C = A @ W^T + bias (3xTF32) --------------
// Block 128m x 128n, 8 warps (32m x 64n each), K-chunk 16.
// smem arrays [128][20] (pad 20 -> conflict-free fragment LDS).
#define TCS 20
__global__ void __launch_bounds__(256, 2) gemm_tc_kernel(
    const float* __restrict__ Ahi, const float* __restrict__ Alo,
    const float* __restrict__ Whi, const float* __restrict__ Wlo,
    const float* __restrict__ bias, float* __restrict__ C,
    int M, int N, int K)
{
    __shared__ float sAh[128 * TCS], sAl[128 * TCS];
    __shared__ float sBh[128 * TCS], sBl[128 * TCS];

    const int tid  = threadIdx.x;
    const int n0   = blockIdx.x * 128;
    const int m0   = blockIdx.y * 128;
    const int w    = tid >> 5, lane = tid & 31;
    const int mw   = (w & 3) * 32, nw = (w >> 2) * 64;
    const int g    = lane >> 2, tig = lane & 3;

    float acc[2][8][4];
#pragma unroll
    for (int mt = 0; mt < 2; mt++)
#pragma unroll
        for (int nt = 0; nt < 8; nt++)
#pragma unroll
            for (int i = 0; i < 4; i++) acc[mt][nt][i] = 0.f;

    for (int kc = 0; kc < K; kc += 16) {
        __syncthreads();
        // stage 4 arrays: 128 rows x 16 floats each
#pragma unroll
        for (int it = 0; it < 2; it++) {
            int item = tid + it * 256;          // 0..511
            int r = item >> 2, qq = (item & 3) * 4;
            size_t ga = (size_t)(m0 + r) * K + kc + qq;
            size_t gb = (size_t)(n0 + r) * K + kc + qq;
            float4 vah = *(const float4*)(Ahi + ga);
            float4 val = *(const float4*)(Alo + ga);
            float4 vbh = *(const float4*)(Whi + gb);
            float4 vbl = *(const float4*)(Wlo + gb);
            *(float4*)(sAh + r * TCS + qq) = vah;
            *(float4*)(sAl + r * TCS + qq) = val;
            *(float4*)(sBh + r * TCS + qq) = vbh;
            *(float4*)(sBl + r * TCS + qq) = vbl;
        }
        __syncthreads();

#pragma unroll
        for (int k8 = 0; k8 < 2; k8++) {
            const int kb = k8 * 8;
            uint32 ah[2][4], al[2][4];
#pragma unroll
            for (int mt = 0; mt < 2; mt++) {
                int mbase = mw + mt * 16;
                ah[mt][0] = __float_as_uint(sAh[(mbase + g) * TCS + kb + tig]);
                ah[mt][1] = __float_as_uint(sAh[(mbase + g + 8) * TCS + kb + tig]);
                ah[mt][2] = __float_as_uint(sAh[(mbase + g) * TCS + kb + tig + 4]);
                ah[mt][3] = __float_as_uint(sAh[(mbase + g + 8) * TCS + kb + tig + 4]);
                al[mt][0] = __float_as_uint(sAl[(mbase + g) * TCS + kb + tig]);
                al[mt][1] = __float_as_uint(sAl[(mbase + g + 8) * TCS + kb + tig]);
                al[mt][2] = __float_as_uint(sAl[(mbase + g) * TCS + kb + tig + 4]);
                al[mt][3] = __float_as_uint(sAl[(mbase + g + 8) * TCS + kb + tig + 4]);
            }
#pragma unroll
            for (int nt = 0; nt < 8; nt++) {
                int nb = (nw + nt * 8 + g) * TCS + kb + tig;
                uint32 bh0 = __float_as_uint(sBh[nb]);
                uint32 bh1 = __float_as_uint(sBh[nb + 4]);
                uint32 bl0 = __float_as_uint(sBl[nb]);
                uint32 bl1 = __float_as_uint(sBl[nb + 4]);
#pragma unroll
                for (int mt = 0; mt < 2; mt++) {
                    mma_tf32(acc[mt][nt], ah[mt], bh0, bh1);   // hi*hi
                    mma_tf32(acc[mt][nt], ah[mt], bl0, bl1);   // hi*lo
                    mma_tf32(acc[mt][nt], al[mt], bh0, bh1);   // lo*hi
                }
            }
        }
    }

    // epilogue: c0,c1 -> (m, n..n+1), c2,c3 -> (m+8, n..n+1)
#pragma unroll
    for (int mt = 0; mt < 2; mt++) {
#pragma unroll
        for (int nt = 0; nt < 8; nt++) {
            int n = n0 + nw + nt * 8 + 2 * tig;
            float2 bb = *(const float2*)&bias[n];
            int m = m0 + mw + mt * 16 + g;
            float2 v0 = make_float2(acc[mt][nt][0] + bb.x, acc[mt][nt][1] + bb.y);
            float2 v1 = make_float2(acc[mt][nt][2] + bb.x, acc[mt][nt][3] + bb.y);
            *(float2*)(C + (size_t)m * N + n)       = v0;
            *(float2*)(C + (size_t)(m + 8) * N + n) = v1;
        }
    }
}

// ---------------- GRU recurrence (R13 exact) ----------------------------------
#define HS 20
#define P4STRIDE 17
#define GRU_SMEM_FLOATS (512 * HS + 16 * 16 * P4STRIDE * 4)
#define GRU_SMEM_BYTES  (GRU_SMEM_FLOATS * 4)

__device__ __forceinline__ unsigned ld_acq(const unsigned* p) {
    unsigned v;
    asm volatile("ld.global.acquire.gpu.u32 %0, [%1];" : "=r"(v) : "l"(p) : "memory");
    return v;
}
__device__ __forceinline__ void st_rel(unsigned* p, unsigned v) {
    asm volatile("st.global.release.gpu.u32 [%0], %1;" :: "l"(p), "r"(v) : "memory");
}

__global__ void __launch_bounds__(512, 1) gru_kernel(
    const float* __restrict__ xg,    // [S][64][1536]
    const float* __restrict__ Whh,   // [1536][512]
    const float* __restrict__ bhh,   // [1536]
    float* __restrict__ ys)          // [S][64][512]
{
    extern __shared__ float sm[];
    float* hsh  = sm;                          // 512*20
    float* part = hsh + 512 * HS;              // 16*16*17*4
    __shared__ unsigned sh_base;

    const int tid = threadIdx.x;
    const int bg  = blockIdx.x & 3;
    const int dg  = blockIdx.x >> 2;
    const int rowBase = bg * 16;
    const int dimBase = dg * 16;

    if (tid == 0) sh_base = *(volatile unsigned*)&g_flags[bg][dg][0];

    // gating role (tid < 256): one thread per (row, dim); h_old in a register
    const int myrow = (tid >> 4) & 15;
    const int mydl  = tid & 15;
    const int mydim = dimBase + mydl;
    float b_r = 0.f, b_z = 0.f, b_n = 0.f;
    float h_old = 0.f;
    if (tid < 256) {
        b_r = bhh[mydim]; b_z = bhh[512 + mydim]; b_n = bhh[1024 + mydim];
    }

    // compute role
    const int w    = tid >> 5;            // warp 0..15, k chunk [32w, 32w+32)
    const int lane = tid & 31;
    const int half = lane >> 4;           // 0: even k, 1: odd k
    const int l    = lane & 15;           // owned dim (local)
    const int k0   = w * 32;

    // W_hh slice -> registers
    float wreg[48];
#pragma unroll
    for (int it = 0; it < 16; ++it) {
        const int k = k0 + 2 * it + half;
#pragma unroll
        for (int g = 0; g < 3; g++)
            wreg[it * 3 + g] = Whh[(size_t)(g * 512 + dimBase + l) * 512 + k];
    }

    __syncthreads();
    const unsigned base = sh_base;

    for (int t = 0; t < S_LEN; ++t) {
        float xr = 0.f, xz = 0.f, xn = 0.f;
        if (tid < 256) {
            size_t xbase = ((size_t)t * 64 + rowBase + myrow) * G3 + mydim;
            xr = xg[xbase]; xz = xg[xbase + 512]; xn = xg[xbase + 1024];
        }

        if (t == 0) {
            for (int idx = lane; idx < 32 * HS; idx += 32)
                hsh[k0 * HS + idx] = 0.f;
            __syncwarp();
        } else {
            const unsigned target = base + (unsigned)t;
            const float4* hsrc4 = (const float4*)(ys + ((size_t)(t - 1) * 64 + rowBase) * HID);
            float4 v[2][2];
#pragma unroll
            for (int j = 0; j < 2; j++) {
                const int c = 2 * w + j;
                const unsigned* fp = &g_flags[bg][c][0];
                while ((int)(ld_acq(fp) - target) < 0) { }
#pragma unroll
                for (int i = 0; i < 2; i++) {
                    int idx = i * 32 + lane;
                    int r = idx & 15, fq = idx >> 4;
                    v[j][i] = __ldcg(hsrc4 + (size_t)r * 128 + c * 4 + fq);
                }
            }
#pragma unroll
            for (int j = 0; j < 2; j++) {
                const int c = 2 * w + j;
#pragma unroll
                for (int i = 0; i < 2; i++) {
                    int idx = i * 32 + lane;
                    int r = idx & 15, fq = idx >> 4;
                    int kb = c * 16 + fq * 4;
                    hsh[(kb + 0) * HS + r] = v[j][i].x;
                    hsh[(kb + 1) * HS + r] = v[j][i].y;
                    hsh[(kb + 2) * HS + r] = v[j][i].z;
                    hsh[(kb + 3) * HS + r] = v[j][i].w;
                }
            }
            __syncwarp();
        }

        ull acc[24];
#pragma unroll
        for (int i = 0; i < 24; i++) acc[i] = 0ULL;
#pragma unroll 4
        for (int it = 0; it < 16; ++it) {
            const int k = k0 + 2 * it + half;
            ull wr2 = dup2(wreg[it * 3 + 0]);
            ull wz2 = dup2(wreg[it * 3 + 1]);
            ull wn2 = dup2(wreg[it * 3 + 2]);
            const float* hk = hsh + k * HS;
            ulonglong2 hq[4];
#pragma unroll
            for (int q = 0; q < 4; q++) hq[q] = *(const ulonglong2*)(hk + 4 * q);
            ull hp[8] = { hq[0].x, hq[0].y, hq[1].x, hq[1].y,
                          hq[2].x, hq[2].y, hq[3].x, hq[3].y };
#pragma unroll
            for (int j = 0; j < 8; j++) {
                ffma2(acc[j * 3 + 0], hp[j], wr2);
                ffma2(acc[j * 3 + 1], hp[j], wz2);
                ffma2(acc[j * 3 + 2], hp[j], wn2);
            }
        }

#pragma unroll
        for (int i = 0; i < 24; i++) {
            ull o = __shfl_down_sync(0xffffffffu, acc[i], 16);
            acc[i] = add2(acc[i], o);
        }

        if (half == 0) {
#pragma unroll
            for (int j = 0; j < 8; j++) {
                float2 r2 = unpk2(acc[j * 3 + 0]);
                float2 z2 = unpk2(acc[j * 3 + 1]);
                float2 n2 = unpk2(acc[j * 3 + 2]);
                float* pp0 = part + (((w * 16 + 2 * j) * P4STRIDE + l) << 2);
                float* pp1 = part + (((w * 16 + 2 * j + 1) * P4STRIDE + l) << 2);
                *(float4*)pp0 = make_float4(r2.x, z2.x, n2.x, 0.f);
                *(float4*)pp1 = make_float4(r2.y, z2.y, n2.y, 0.f);
            }
        }
        __syncthreads();

        if (tid < 256) {
            float hr = b_r, hz = b_z, hn = b_n;
#pragma unroll
            for (int kk = 0; kk < 16; kk++) {
                float4 p = *(const float4*)(part +
                    (((kk * 16 + myrow) * P4STRIDE + mydl) << 2));
                hr += p.x; hz += p.y; hn += p.z;
            }
            float er = __expf(-(xr + hr));
            float rr = __fdividef(1.f, 1.f + er);
            float ez = __expf(-(xz + hz));
            float zz = __fdividef(1.f, 1.f + ez);
            float an = xn + rr * hn;
            float e2 = __expf(2.f * an);
            float nn = 1.f - __fdividef(2.f, e2 + 1.f);   // tanh(an)
            float hnew = (1.f - zz) * nn + zz * h_old;
            h_old = hnew;
            ys[((size_t)t * 64 + rowBase + myrow) * HID + mydim] = hnew;
        }

        __syncthreads();
        if (tid == 0) st_rel(&g_flags[bg][dg][0], base + (unsigned)t + 1u);
    }
}

// ---------------- final FC + sigmoid ----------------------------------------
__global__ void fc_kernel(const float* __restrict__ ys,
                          const float* __restrict__ Wfc,
                          const float* __restrict__ bfc,
                          float* __restrict__ out) {
    int b = blockIdx.x, tid = threadIdx.x;
    const float* h = ys + ((size_t)(S_LEN - 1) * 64 + b) * HID;
    float s = 0.f;
    for (int i = tid; i < HID; i += 128) s += h[i] * Wfc[i];
#pragma unroll
    for (int o = 16; o; o >>= 1) s += __shfl_down_sync(0xffffffffu, s, o);
    __shared__ float ps[4];
    if ((tid & 31) == 0) ps[tid >> 5] = s;
    __syncthreads();
    if (tid == 0) {
        float v = ps[0] + ps[1] + ps[2] + ps[3] + bfc[0];
        out[b] = 1.f / (1.f + expf(-v));
    }
}

// ---------------- launch ----------------------------------------------------
extern "C" void kernel_launch(void* const* d_in, const int* in_sizes, int n_in,
                              void* d_out, int out_size) {
    (void)in_sizes; (void)n_in; (void)out_size;
    const int*   x    = (const int*)  d_in[0];
    const float* emb  = (const float*)d_in[1];
    const float* Wih0 = (const float*)d_in[2];
    const float* Whh0 = (const float*)d_in[3];
    const float* bih0 = (const float*)d_in[4];
    const float* bhh0 = (const float*)d_in[5];
    const float* Wih1 = (const float*)d_in[6];
    const float* Whh1 = (const float*)d_in[7];
    const float* bih1 = (const float*)d_in[8];
    const float* bhh1 = (const float*)d_in[9];
    const float* Wfc  = (const float*)d_in[10];
    const float* bfc  = (const float*)d_in[11];
    float* out = (float*)d_out;

    float *ahi, *alo, *w0hi, *w0lo, *w1hi, *w1lo, *xgbuf, *ysbuf;
    cudaGetSymbolAddress((void**)&ahi,  g_ahi);
    cudaGetSymbolAddress((void**)&alo,  g_alo);
    cudaGetSymbolAddress((void**)&w0hi, g_w0hi);
    cudaGetSymbolAddress((void**)&w0lo, g_w0lo);
    cudaGetSymbolAddress((void**)&w1hi, g_w1hi);
    cudaGetSymbolAddress((void**)&w1lo, g_w1lo);
    cudaGetSymbolAddress((void**)&xgbuf, g_xg);
    cudaGetSymbolAddress((void**)&ysbuf, g_ys);

    cudaFuncSetAttribute(gru_kernel, cudaFuncAttributeMaxDynamicSharedMemorySize,
                         GRU_SMEM_BYTES);

    // weight splits (small)
    split_kernel<<<(G3 * EMB_D / 4 + 255) / 256, 256>>>(Wih0, w0hi, w0lo, G3 * EMB_D / 4);
    split_kernel<<<(G3 * HID / 4 + 255) / 256, 256>>>(Wih1, w1hi, w1lo, G3 * HID / 4);

    // embedding gather fused with tf32 split
    embed_split_kernel<<<4096, 256>>>(x, emb, ahi, alo);

    gemm_tc_kernel<<<dim3(G3 / 128, M_ROWS / 128), 256>>>(
        ahi, alo, w0hi, w0lo, bih0, xgbuf, M_ROWS, G3, EMB_D);
    gru_kernel<<<128, 512, GRU_SMEM_BYTES>>>(xgbuf, Whh0, bhh0, ysbuf);

    // split ys for layer-2 GEMM
    split_kernel<<<((size_t)M_ROWS * HID / 4 + 255) / 256, 256>>>(
        ysbuf, ahi, alo, M_ROWS * HID / 4);
    gemm_tc_kernel<<<dim3(G3 / 128, M_ROWS / 128), 256>>>(
        ahi, alo, w1hi, w1lo, bih1, xgbuf, M_ROWS, G3, HID);
    gru_kernel<<<128, 512, GRU_SMEM_BYTES>>>(xgbuf, Whh1, bhh1, ysbuf);

    fc_kernel<<<64, 128>>>(ysbuf, Wfc, bfc, out);
}